// round 2
// baseline (speedup 1.0000x reference)
#include <cuda_runtime.h>
#include <cstdint>

#define BS 8
#define SEQ 16
#define HW 1024
#define CK 256
#define CV 3
#define NSTEP 15
#define BQ 64
#define BK 64
#define NKT (HW / BK)

// ---------------- persistent scratch (__device__ globals; no cudaMalloc) ----
__device__ __align__(256) float g_KT[BS * SEQ * CK * HW];  // 134 MB: k transposed [b][s][c][p]
__device__ __align__(256) float g_MT[BS * CK * HW];        // 8 MB: m_k transposed [b][c][p]
__device__ __align__(256) float g_mv[BS * HW * 4];         // m_v padded to 4
__device__ __align__(256) float g_pv[2][BS * HW * 4];      // prev_v double buffer
__device__ int g_mask[BS * SEQ];                           // decoded seq_mask

// ---------------- helpers ---------------------------------------------------
__device__ __forceinline__ void cp16(float* dst_smem, const float* src_g) {
    unsigned sa = (unsigned)__cvta_generic_to_shared(dst_smem);
    asm volatile("cp.async.cg.shared.global [%0], [%1], 16;\n" ::"r"(sa), "l"(src_g));
}
__device__ __forceinline__ void cp_commit() { asm volatile("cp.async.commit_group;\n"); }
__device__ __forceinline__ void cp_wait0() { asm volatile("cp.async.wait_group 0;\n"); }
__device__ __forceinline__ void cp_wait1() { asm volatile("cp.async.wait_group 1;\n"); }

#define FMA2(acc, a, b) \
    asm("fma.rn.f32x2 %0, %1, %2, %0;" : "+l"(acc) : "l"(a), "l"(b))

__device__ __forceinline__ unsigned long long dup32(float x) {
    unsigned long long r;
    unsigned xb = __float_as_uint(x);
    asm("mov.b64 %0, {%1, %1};" : "=l"(r) : "r"(xb));
    return r;
}
__device__ __forceinline__ float lo64(unsigned long long x) {
    return __uint_as_float((unsigned)(x & 0xffffffffull));
}
__device__ __forceinline__ float hi64(unsigned long long x) {
    return __uint_as_float((unsigned)(x >> 32));
}

// ---------------- kernel: decode seq_mask with dtype sniffing ----------------
// jax bool may arrive as int32, float32, or uint8. Detect from the first 128
// bytes (valid for all candidates), then decode all BS*SEQ entries.
__global__ void mask_decode_kernel(const unsigned char* __restrict__ m) {
    __shared__ int not_i32, not_f32;
    int t = threadIdx.x;  // 128 threads
    if (t == 0) { not_i32 = 0; not_f32 = 0; }
    __syncthreads();
    if (t < 32) {
        int w = ((const int*)m)[t];  // first 128 bytes only
        if (w != 0 && w != 1) not_i32 = 1;
        if (w != 0 && w != 0x3F800000) not_f32 = 1;
    }
    __syncthreads();
    int val;
    if (!not_i32)
        val = (((const int*)m)[t] != 0);        // int32 0/1
    else if (!not_f32)
        val = (((const int*)m)[t] != 0);        // float32 0.0/1.0 (bits nonzero)
    else
        val = (m[t] != 0);                      // bool/uint8
    g_mask[t] = val;
}

// ---------------- kernel: transpose all k into KT (once per launch) ---------
__global__ void kt_transpose_kernel(const float* __restrict__ k) {
    __shared__ float tile[32][33];
    int bs_ = blockIdx.z;                     // b*SEQ + s
    int p0 = blockIdx.x * 32;
    int c0 = blockIdx.y * 32;
    const float* src = k + (size_t)bs_ * HW * CK;
    float* dst = g_KT + (size_t)bs_ * CK * HW;
    int tx = threadIdx.x, ty = threadIdx.y;   // (32, 8)
#pragma unroll
    for (int j = 0; j < 32; j += 8)
        tile[ty + j][tx] = src[(size_t)(p0 + ty + j) * CK + c0 + tx];
    __syncthreads();
#pragma unroll
    for (int j = 0; j < 32; j += 8)
        dst[(size_t)(c0 + ty + j) * HW + p0 + tx] = tile[tx][ty + j];
}

// ---------------- kernel: init states ---------------------------------------
__global__ void init_kernel(const float* __restrict__ v) {
    int e = blockIdx.x * blockDim.x + threadIdx.x;   // 0 .. 524287 (float4 over MT)
    float4 z = make_float4(0.f, 0.f, 0.f, 0.f);
    ((float4*)g_MT)[e] = z;
    int b = e >> 16;
    int rem = e & 65535;
    int c = rem >> 8;
    int p4 = rem & 255;
    if (c == 0) {
#pragma unroll
        for (int u = 0; u < 4; u++) {
            int p = p4 * 4 + u;
            ((float4*)g_mv)[b * HW + p] = z;
            const float* vp = v + ((size_t)(b * SEQ + 0) * HW + p) * CV;
            float4 pv;
            pv.x = vp[0]; pv.y = vp[1]; pv.z = vp[2]; pv.w = 0.f;
            ((float4*)g_pv[0])[b * HW + p] = pv;
        }
    }
}

// ---------------- kernel: per-step state update (m_k in transposed space) ---
__global__ void update_kernel(const float* __restrict__ att,
                              const float* __restrict__ v,
                              float* __restrict__ gt_out, int i, int cur) {
    int e = blockIdx.x * blockDim.x + threadIdx.x;
    int b = e >> 16;
    int rem = e & 65535;
    int c = rem >> 8;
    int p4 = rem & 255;
    int p = p4 * 4;

    float4 a4 = *(const float4*)(att + ((size_t)(b * SEQ + i) * HW + p));
    float4 g4;
    g4.x = 1.f / (1.f + __expf(-a4.x));
    g4.y = 1.f / (1.f + __expf(-a4.y));
    g4.z = 1.f / (1.f + __expf(-a4.z));
    g4.w = 1.f / (1.f + __expf(-a4.w));

    const float4 kt4 = *(const float4*)(g_KT + ((size_t)((b * SEQ + i) * CK + c)) * HW + p);
    float4* mtp = (float4*)(g_MT + ((size_t)(b * CK + c)) * HW + p);
    float4 mt = *mtp;
    mt.x = g4.x * kt4.x + (1.f - g4.x) * mt.x;
    mt.y = g4.y * kt4.y + (1.f - g4.y) * mt.y;
    mt.z = g4.z * kt4.z + (1.f - g4.z) * mt.z;
    mt.w = g4.w * kt4.w + (1.f - g4.w) * mt.w;
    *mtp = mt;

    if (c == 0) {
        float ga[4] = {g4.x, g4.y, g4.z, g4.w};
#pragma unroll
        for (int u = 0; u < 4; u++) {
            int pp = p + u;
            float gv = ga[u];
            float4 pv = ((float4*)g_pv[cur])[b * HW + pp];
            float4* mvp = &((float4*)g_mv)[b * HW + pp];
            float4 mv = *mvp;
            mv.x = gv * pv.x + (1.f - gv) * mv.x;
            mv.y = gv * pv.y + (1.f - gv) * mv.y;
            mv.z = gv * pv.z + (1.f - gv) * mv.z;
            *mvp = mv;
            // gt output = v[:, i+1]
            const float* vn = v + ((size_t)(b * SEQ + i + 1) * HW + pp) * CV;
            float* gtp = gt_out + ((size_t)(b * NSTEP + i) * HW + pp) * CV;
            gtp[0] = vn[0]; gtp[1] = vn[1]; gtp[2] = vn[2];
        }
    }
}

// ---------------- kernel: fused double-softmax attention step ---------------
// block: 256 threads = 16 (tx, keys) x 16 (ty, queries). Thread tile: 4q x 4k.
__global__ __launch_bounds__(256, 1) void attend_kernel(
    const float* __restrict__ v, float* __restrict__ out_v, int i, int cur) {
    extern __shared__ float smem[];
    float* Qs = smem;                 // [256][64]
    float* Ks0 = Qs + CK * BQ;        // [256][64]
    float* Ks1 = Ks0 + CK * BK;       // [256][64]
    float* Vs0 = Ks1 + CK * BK;       // [64][4]
    float* Vs1 = Vs0 + BK * 4;        // [64][4]

    int t = threadIdx.x;
    int tx = t & 15, ty = t >> 4;
    int qt = blockIdx.x, b = blockIdx.y;
    int qbase = qt * BQ;

    // Load Q tile (transposed source: g_KT slab s = i+1), conflict-free STS.128
    {
        const float* Qg = g_KT + (size_t)((b * SEQ + i + 1) * CK) * HW;
#pragma unroll
        for (int j = 0; j < 16; j++) {
            int idx = j * 256 + t;
            int c = idx >> 4, q4 = idx & 15;
            *(float4*)&Qs[c * BQ + q4 * 4] =
                *(const float4*)&Qg[(size_t)c * HW + qbase + q4 * 4];
        }
    }
    __syncthreads();

    float rec[4][3];
#pragma unroll
    for (int r = 0; r < 4; r++) rec[r][0] = rec[r][1] = rec[r][2] = 0.f;

    for (int pass = 0; pass < 2; pass++) {
        const float* Ksrc = pass ? (g_MT + (size_t)b * CK * HW)
                                 : (g_KT + (size_t)((b * SEQ + i) * CK) * HW);
        const float* Vsrc = pass ? (g_mv + (size_t)b * HW * 4)
                                 : (g_pv[cur] + (size_t)b * HW * 4);
        float wgt = pass ? 0.1f : 0.9f;

        float m[4], ssum[4], acc[4][3];
#pragma unroll
        for (int r = 0; r < 4; r++) {
            m[r] = -1e30f; ssum[r] = 0.f;
            acc[r][0] = acc[r][1] = acc[r][2] = 0.f;
        }

        // prefetch ktile 0 -> buffer 0
        {
            int kbase = 0;
#pragma unroll
            for (int j = 0; j < 16; j++) {
                int idx = j * 256 + t;
                int c = idx >> 4, q4 = idx & 15;
                cp16(&Ks0[c * BK + q4 * 4], &Ksrc[(size_t)c * HW + kbase + q4 * 4]);
            }
            if (t < BK) cp16(&Vs0[t * 4], &Vsrc[(size_t)(kbase + t) * 4]);
            cp_commit();
        }

        for (int kt = 0; kt < NKT; kt++) {
            int buf = kt & 1;
            if (kt + 1 < NKT) {
                float* Kd = (buf ^ 1) ? Ks1 : Ks0;
                float* Vd = (buf ^ 1) ? Vs1 : Vs0;
                int kbase = (kt + 1) * BK;
#pragma unroll
                for (int j = 0; j < 16; j++) {
                    int idx = j * 256 + t;
                    int c = idx >> 4, q4 = idx & 15;
                    cp16(&Kd[c * BK + q4 * 4], &Ksrc[(size_t)c * HW + kbase + q4 * 4]);
                }
                if (t < BK) cp16(&Vd[t * 4], &Vsrc[(size_t)(kbase + t) * 4]);
                cp_commit();
                cp_wait1();
            } else {
                cp_wait0();
            }
            __syncthreads();

            const float* Ks = buf ? Ks1 : Ks0;
            const float* Vs = buf ? Vs1 : Vs0;
            const float* qptr = Qs + 4 * ty;
            const float* kptr = Ks + 4 * tx;

            // ---- S = Q_tile . K_tile^T over 256 channels (packed f32x2) ----
            unsigned long long a00 = 0, a01 = 0, a10 = 0, a11 = 0;
            unsigned long long a20 = 0, a21 = 0, a30 = 0, a31 = 0;
#pragma unroll 8
            for (int cc = 0; cc < CK; cc++) {
                const ulonglong2 qv = *(const ulonglong2*)(qptr + cc * BQ);
                const float4 kv = *(const float4*)(kptr + cc * BK);
                unsigned long long kd0 = dup32(kv.x);
                unsigned long long kd1 = dup32(kv.y);
                unsigned long long kd2 = dup32(kv.z);
                unsigned long long kd3 = dup32(kv.w);
                FMA2(a00, kd0, qv.x); FMA2(a01, kd0, qv.y);
                FMA2(a10, kd1, qv.x); FMA2(a11, kd1, qv.y);
                FMA2(a20, kd2, qv.x); FMA2(a21, kd2, qv.y);
                FMA2(a30, kd3, qv.x); FMA2(a31, kd3, qv.y);
            }
            // unpack s[row][col]
            float s[4][4];
            s[0][0] = lo64(a00); s[1][0] = hi64(a00); s[2][0] = lo64(a01); s[3][0] = hi64(a01);
            s[0][1] = lo64(a10); s[1][1] = hi64(a10); s[2][1] = lo64(a11); s[3][1] = hi64(a11);
            s[0][2] = lo64(a20); s[1][2] = hi64(a20); s[2][2] = lo64(a21); s[3][2] = hi64(a21);
            s[0][3] = lo64(a30); s[1][3] = hi64(a30); s[2][3] = lo64(a31); s[3][3] = hi64(a31);

            // ---- online softmax update (row reductions across the 16 tx lanes)
            float mx[4];
#pragma unroll
            for (int r = 0; r < 4; r++)
                mx[r] = fmaxf(fmaxf(s[r][0], s[r][1]), fmaxf(s[r][2], s[r][3]));
#pragma unroll
            for (int o = 1; o < 16; o <<= 1) {
#pragma unroll
                for (int r = 0; r < 4; r++)
                    mx[r] = fmaxf(mx[r], __shfl_xor_sync(0xffffffffu, mx[r], o, 16));
            }
#pragma unroll
            for (int r = 0; r < 4; r++) {
                float mn = fmaxf(m[r], mx[r]);
                float corr = __expf(m[r] - mn);
                m[r] = mn;
                ssum[r] *= corr;
                acc[r][0] *= corr; acc[r][1] *= corr; acc[r][2] *= corr;
#pragma unroll
                for (int c = 0; c < 4; c++) {
                    float p = __expf(s[r][c] - mn);
                    ssum[r] += p;
                    float4 vv = *(const float4*)&Vs[(4 * tx + c) * 4];
                    acc[r][0] += p * vv.x;
                    acc[r][1] += p * vv.y;
                    acc[r][2] += p * vv.z;
                }
            }
            __syncthreads();
        }

        // ---- final cross-lane reduction of partial sums / accumulators ----
#pragma unroll
        for (int o = 1; o < 16; o <<= 1) {
#pragma unroll
            for (int r = 0; r < 4; r++) {
                ssum[r] += __shfl_xor_sync(0xffffffffu, ssum[r], o, 16);
                acc[r][0] += __shfl_xor_sync(0xffffffffu, acc[r][0], o, 16);
                acc[r][1] += __shfl_xor_sync(0xffffffffu, acc[r][1], o, 16);
                acc[r][2] += __shfl_xor_sync(0xffffffffu, acc[r][2], o, 16);
            }
        }
#pragma unroll
        for (int r = 0; r < 4; r++) {
            float inv = wgt / ssum[r];
            rec[r][0] += acc[r][0] * inv;
            rec[r][1] += acc[r][1] * inv;
            rec[r][2] += acc[r][2] * inv;
        }
    }

    // ---- epilogue: write out_v, update prev_v (masked) --------------------
    if (tx == 0) {
        bool mk = g_mask[b * SEQ + i] != 0;
        float* pvn = g_pv[cur ^ 1] + (size_t)b * HW * 4;
#pragma unroll
        for (int r = 0; r < 4; r++) {
            int q = qbase + 4 * ty + r;
            const float* vp = v + ((size_t)(b * SEQ + i) * HW + q) * CV;
            float4 o;
            o.x = mk ? vp[0] : rec[r][0];
            o.y = mk ? vp[1] : rec[r][1];
            o.z = mk ? vp[2] : rec[r][2];
            o.w = 0.f;
            ((float4*)pvn)[q] = o;
            float* op = out_v + ((size_t)(b * NSTEP + i) * HW + q) * CV;
            op[0] = rec[r][0]; op[1] = rec[r][1]; op[2] = rec[r][2];
        }
    }
}

// ---------------- host launcher ---------------------------------------------
extern "C" void kernel_launch(void* const* d_in, const int* in_sizes, int n_in,
                              void* d_out, int out_size) {
    const float* k = (const float*)d_in[0];
    const float* v = (const float*)d_in[1];
    const float* att = (const float*)d_in[2];
    const unsigned char* mask = (const unsigned char*)d_in[3];
    float* out_v = (float*)d_out;
    float* gt = out_v + (size_t)out_size / 2;

    int smem_bytes = (CK * BQ + 2 * CK * BK + 2 * BK * 4) * (int)sizeof(float);  // 198656
    cudaFuncSetAttribute(attend_kernel, cudaFuncAttributeMaxDynamicSharedMemorySize,
                         smem_bytes);

    mask_decode_kernel<<<1, BS * SEQ>>>(mask);
    kt_transpose_kernel<<<dim3(HW / 32, CK / 32, BS * SEQ), dim3(32, 8)>>>(k);
    init_kernel<<<2048, 256>>>(v);

    for (int i = 0; i < NSTEP; i++) {
        int cur = i & 1;
        update_kernel<<<2048, 256>>>(att, v, gt, i, cur);
        attend_kernel<<<dim3(HW / BQ, BS), 256, smem_bytes>>>(v, out_v, i, cur);
    }
}

// round 3
// speedup vs baseline: 1.0328x; 1.0328x over previous
#include <cuda_runtime.h>
#include <cstdint>

#define BS 8
#define SEQ 16
#define HW 1024
#define CK 256
#define CV 3
#define NSTEP 15
#define BQ 64
#define BK 256
#define NKT (HW / BK)   // 4 per pass
#define CCH 64          // channel chunk
#define NCH (CK / CCH)  // 4
#define GSTR 516        // padded group stride (floats): 64*8 + 4

// ---------------- persistent scratch ----------------------------------------
__device__ __align__(256) float g_KT[BS * SEQ * CK * HW];  // k transposed [b][s][c][p]
__device__ __align__(256) float g_MT[BS * CK * HW];        // m_k transposed [b][c][p]
__device__ __align__(256) float g_mv[BS * HW * 4];         // m_v padded to 4
__device__ __align__(256) float g_pv[2][BS * HW * 4];      // prev_v double buffer
__device__ int g_mask[BS * SEQ];

// ---------------- helpers ---------------------------------------------------
__device__ __forceinline__ void cp16(float* dst_smem, const float* src_g) {
    unsigned sa = (unsigned)__cvta_generic_to_shared(dst_smem);
    asm volatile("cp.async.cg.shared.global [%0], [%1], 16;\n" ::"r"(sa), "l"(src_g));
}
__device__ __forceinline__ void cp_commit() { asm volatile("cp.async.commit_group;\n"); }
__device__ __forceinline__ void cp_wait0() { asm volatile("cp.async.wait_group 0;\n"); }
__device__ __forceinline__ void cp_wait1() { asm volatile("cp.async.wait_group 1;\n"); }

#define FMA2(acc, a, b) \
    asm("fma.rn.f32x2 %0, %1, %2, %0;" : "+l"(acc) : "l"(a), "l"(b))

__device__ __forceinline__ unsigned long long dup32(float x) {
    unsigned long long r;
    unsigned xb = __float_as_uint(x);
    asm("mov.b64 %0, {%1, %1};" : "=l"(r) : "r"(xb));
    return r;
}
__device__ __forceinline__ float lo64(unsigned long long x) {
    return __uint_as_float((unsigned)(x & 0xffffffffull));
}
__device__ __forceinline__ float hi64(unsigned long long x) {
    return __uint_as_float((unsigned)(x >> 32));
}

// ---------------- mask decode (dtype sniffing, worked in R2) ----------------
__global__ void mask_decode_kernel(const unsigned char* __restrict__ m) {
    __shared__ int not_i32;
    int t = threadIdx.x;  // 128 threads
    if (t == 0) not_i32 = 0;
    __syncthreads();
    if (t < 32) {
        int w = ((const int*)m)[t];
        if (w != 0 && w != 1) not_i32 = 1;
    }
    __syncthreads();
    int val;
    if (!not_i32)
        val = (((const int*)m)[t] != 0);
    else
        val = (m[t] != 0);
    g_mask[t] = val;
}

// ---------------- transpose k -> KT ------------------------------------------
__global__ void kt_transpose_kernel(const float* __restrict__ k) {
    __shared__ float tile[32][33];
    int bs_ = blockIdx.z;
    int p0 = blockIdx.x * 32;
    int c0 = blockIdx.y * 32;
    const float* src = k + (size_t)bs_ * HW * CK;
    float* dst = g_KT + (size_t)bs_ * CK * HW;
    int tx = threadIdx.x, ty = threadIdx.y;  // (32, 8)
#pragma unroll
    for (int j = 0; j < 32; j += 8)
        tile[ty + j][tx] = src[(size_t)(p0 + ty + j) * CK + c0 + tx];
    __syncthreads();
#pragma unroll
    for (int j = 0; j < 32; j += 8)
        dst[(size_t)(c0 + ty + j) * HW + p0 + tx] = tile[tx][ty + j];
}

// ---------------- gt copy: gt = v[:, 1:] (contiguous per-batch) --------------
__global__ void gt_copy_kernel(const float* __restrict__ v, float* __restrict__ gt) {
    int e = blockIdx.x * blockDim.x + threadIdx.x;  // 92160 float4
    int b = e / (NSTEP * HW * CV / 4);
    int r = e - b * (NSTEP * HW * CV / 4);
    const float4* src = (const float4*)(v + ((size_t)b * SEQ + 1) * HW * CV);
    float4* dst = (float4*)(gt + (size_t)b * NSTEP * HW * CV);
    dst[r] = src[r];
}

// ---------------- init states ------------------------------------------------
__global__ void init_kernel(const float* __restrict__ v) {
    int e = blockIdx.x * blockDim.x + threadIdx.x;  // float4 over MT
    float4 z = make_float4(0.f, 0.f, 0.f, 0.f);
    ((float4*)g_MT)[e] = z;
    int b = e >> 16;
    int rem = e & 65535;
    int c = rem >> 8;
    int p4 = rem & 255;
    if (c == 0) {
#pragma unroll
        for (int u = 0; u < 4; u++) {
            int p = p4 * 4 + u;
            ((float4*)g_mv)[b * HW + p] = z;
            const float* vp = v + ((size_t)(b * SEQ + 0) * HW + p) * CV;
            float4 pv;
            pv.x = vp[0]; pv.y = vp[1]; pv.z = vp[2]; pv.w = 0.f;
            ((float4*)g_pv[0])[b * HW + p] = pv;
        }
    }
}

// ---------------- per-step state update --------------------------------------
__global__ void update_kernel(const float* __restrict__ att, int i, int cur) {
    int e = blockIdx.x * blockDim.x + threadIdx.x;
    int b = e >> 16;
    int rem = e & 65535;
    int c = rem >> 8;
    int p = (rem & 255) * 4;

    float4 a4 = *(const float4*)(att + ((size_t)(b * SEQ + i) * HW + p));
    float4 g4;
    g4.x = 1.f / (1.f + __expf(-a4.x));
    g4.y = 1.f / (1.f + __expf(-a4.y));
    g4.z = 1.f / (1.f + __expf(-a4.z));
    g4.w = 1.f / (1.f + __expf(-a4.w));

    const float4 kt4 = *(const float4*)(g_KT + ((size_t)((b * SEQ + i) * CK + c)) * HW + p);
    float4* mtp = (float4*)(g_MT + ((size_t)(b * CK + c)) * HW + p);
    float4 mt = *mtp;
    mt.x = g4.x * kt4.x + (1.f - g4.x) * mt.x;
    mt.y = g4.y * kt4.y + (1.f - g4.y) * mt.y;
    mt.z = g4.z * kt4.z + (1.f - g4.z) * mt.z;
    mt.w = g4.w * kt4.w + (1.f - g4.w) * mt.w;
    *mtp = mt;

    if (c == 0) {
        float ga[4] = {g4.x, g4.y, g4.z, g4.w};
#pragma unroll
        for (int u = 0; u < 4; u++) {
            int pp = p + u;
            float gv = ga[u];
            float4 pv = ((float4*)g_pv[cur])[b * HW + pp];
            float4* mvp = &((float4*)g_mv)[b * HW + pp];
            float4 mv = *mvp;
            mv.x = gv * pv.x + (1.f - gv) * mv.x;
            mv.y = gv * pv.y + (1.f - gv) * mv.y;
            mv.z = gv * pv.z + (1.f - gv) * mv.z;
            *mvp = mv;
        }
    }
}

// ---------------- fused double-softmax attention (8x8 register blocked) ------
// 256 threads: warp ty (0..7) owns q rows [ty*8, ty*8+8); lane tx owns k cols
// [tx*8, tx*8+8) of the BK=256 key tile. Channels streamed in 64-chunks.
__global__ __launch_bounds__(256, 1) void attend_kernel(
    const float* __restrict__ vin, float* __restrict__ out_v, int i, int cur) {
    extern __shared__ float smem[];
    float* Qs = smem;                         // [256][64]   16384 floats
    float* Kb0 = Qs + CK * BQ;                // 32 groups * 516
    float* Kb1 = Kb0 + 32 * GSTR;
    float* Vb0 = Kb1 + 32 * GSTR;             // [256][4]
    float* Vb1 = Vb0 + BK * 4;

    int t = threadIdx.x;
    int tx = t & 31, ty = t >> 5;
    int qt = blockIdx.x, b = blockIdx.y;
    int qbase = qt * BQ;

    const float* Ksrc0 = g_KT + (size_t)((b * SEQ + i) * CK) * HW;
    const float* Ksrc1 = g_MT + (size_t)b * CK * HW;
    const float* Vsrc0 = g_pv[cur] + (size_t)b * HW * 4;
    const float* Vsrc1 = g_mv + (size_t)b * HW * 4;

    // ---- load Q tile [256 c][64 q] ----
    {
        const float* Qg = g_KT + (size_t)((b * SEQ + i + 1) * CK) * HW;
#pragma unroll
        for (int j = 0; j < 16; j++) {
            int idx = j * 256 + t;
            int c = idx >> 4, q4 = idx & 15;
            *(float4*)&Qs[c * BQ + q4 * 4] =
                *(const float4*)&Qg[(size_t)c * HW + qbase + q4 * 4];
        }
    }

    // ---- prefetch helper (chunk ci: pass=ci>>4, kt=(ci>>2)&3, ch=ci&3) ----
    auto prefetch = [&](int ci) {
        int pass = ci >> 4;
        int kt = (ci >> 2) & 3;
        int ch = ci & 3;
        const float* Ks = pass ? Ksrc1 : Ksrc0;
        float* Kd = (ci & 1) ? Kb1 : Kb0;
        int kbase = kt * BK;
        int c0 = ch * CCH;
#pragma unroll
        for (int j = 0; j < 16; j++) {
            int idx = j * 256 + t;
            int g = idx & 31;
            int half = (idx >> 5) & 1;
            int cc = idx >> 6;
            cp16(Kd + g * GSTR + cc * 8 + half * 4,
                 Ks + (size_t)(c0 + cc) * HW + kbase + g * 8 + half * 4);
        }
        if (ch == 0) {
            const float* Vsp = pass ? Vsrc1 : Vsrc0;
            float* Vd = (kt & 1) ? Vb1 : Vb0;
            cp16(Vd + t * 4, Vsp + (size_t)(kbase + t) * 4);
        }
    };

    prefetch(0);
    cp_commit();
    __syncthreads();  // Qs visible

    float rec[8][3];
#pragma unroll
    for (int r = 0; r < 8; r++) rec[r][0] = rec[r][1] = rec[r][2] = 0.f;

    float m[8], ssum[8], vacc[8][3];
    unsigned long long acc[4][8];

#pragma unroll 1
    for (int ci = 0; ci < 32; ci++) {
        int kt = (ci >> 2) & 3;
        int ch = ci & 3;
        int kti = ci >> 2;  // 0..7 global ktile

        if (ch == 0) {
#pragma unroll
            for (int p = 0; p < 4; p++)
#pragma unroll
                for (int j = 0; j < 8; j++) acc[p][j] = 0ull;
            if (kt == 0) {  // pass start
#pragma unroll
                for (int r = 0; r < 8; r++) {
                    m[r] = -1e30f; ssum[r] = 0.f;
                    vacc[r][0] = vacc[r][1] = vacc[r][2] = 0.f;
                }
            }
        }

        if (ci + 1 < 32) {
            prefetch(ci + 1);
            cp_commit();
            cp_wait1();
        } else {
            cp_wait0();
        }
        __syncthreads();  // chunk ci data visible to all

        // ---- 64-channel FMA block ----
        {
            const float* Kp = ((ci & 1) ? Kb1 : Kb0) + tx * GSTR;
            const float* Qp = Qs + (ch * CCH) * BQ + ty * 8;
#pragma unroll 4
            for (int cc = 0; cc < CCH; cc++) {
                float4 k0 = *(const float4*)(Kp + cc * 8);
                float4 k1 = *(const float4*)(Kp + cc * 8 + 4);
                ulonglong2 qA = *(const ulonglong2*)(Qp + cc * BQ);
                ulonglong2 qB = *(const ulonglong2*)(Qp + cc * BQ + 4);
                unsigned long long kd[8];
                kd[0] = dup32(k0.x); kd[1] = dup32(k0.y);
                kd[2] = dup32(k0.z); kd[3] = dup32(k0.w);
                kd[4] = dup32(k1.x); kd[5] = dup32(k1.y);
                kd[6] = dup32(k1.z); kd[7] = dup32(k1.w);
#pragma unroll
                for (int j = 0; j < 8; j++) {
                    FMA2(acc[0][j], kd[j], qA.x);
                    FMA2(acc[1][j], kd[j], qA.y);
                    FMA2(acc[2][j], kd[j], qB.x);
                    FMA2(acc[3][j], kd[j], qB.y);
                }
            }
        }

        // ---- ktile complete: online softmax update ----
        if (ch == 3) {
            const float* Vs = (kt & 1) ? Vb1 : Vb0;
            float4 vv[8];
#pragma unroll
            for (int j = 0; j < 8; j++)
                vv[j] = *(const float4*)&Vs[(tx * 8 + j) * 4];

#pragma unroll
            for (int r = 0; r < 8; r++) {
                int p = r >> 1;
                float sv[8];
#pragma unroll
                for (int j = 0; j < 8; j++)
                    sv[j] = (r & 1) ? hi64(acc[p][j]) : lo64(acc[p][j]);
                float mx = sv[0];
#pragma unroll
                for (int j = 1; j < 8; j++) mx = fmaxf(mx, sv[j]);
#pragma unroll
                for (int o = 16; o > 0; o >>= 1)
                    mx = fmaxf(mx, __shfl_xor_sync(0xffffffffu, mx, o));
                float mn = fmaxf(m[r], mx);
                float corr = __expf(m[r] - mn);
                m[r] = mn;
                ssum[r] *= corr;
                vacc[r][0] *= corr; vacc[r][1] *= corr; vacc[r][2] *= corr;
#pragma unroll
                for (int j = 0; j < 8; j++) {
                    float pw = __expf(sv[j] - mn);
                    ssum[r] += pw;
                    vacc[r][0] += pw * vv[j].x;
                    vacc[r][1] += pw * vv[j].y;
                    vacc[r][2] += pw * vv[j].z;
                }
            }

            if (kt == 3) {  // pass end: cross-lane reduce + fold into rec
                float wgt = (kti >> 2) ? 0.1f : 0.9f;
#pragma unroll
                for (int o = 16; o > 0; o >>= 1) {
#pragma unroll
                    for (int r = 0; r < 8; r++) {
                        ssum[r] += __shfl_xor_sync(0xffffffffu, ssum[r], o);
                        vacc[r][0] += __shfl_xor_sync(0xffffffffu, vacc[r][0], o);
                        vacc[r][1] += __shfl_xor_sync(0xffffffffu, vacc[r][1], o);
                        vacc[r][2] += __shfl_xor_sync(0xffffffffu, vacc[r][2], o);
                    }
                }
#pragma unroll
                for (int r = 0; r < 8; r++) {
                    float inv = wgt / ssum[r];
                    rec[r][0] += vacc[r][0] * inv;
                    rec[r][1] += vacc[r][1] * inv;
                    rec[r][2] += vacc[r][2] * inv;
                }
            }
        }
        __syncthreads();  // all warps done with buf[ci&1] before overwrite
    }

    // ---- epilogue: write out_v, update prev_v (masked) ----
    if (tx == 0) {
        bool mk = g_mask[b * SEQ + i] != 0;
        float* pvn = g_pv[cur ^ 1] + (size_t)b * HW * 4;
#pragma unroll
        for (int r = 0; r < 8; r++) {
            int q = qbase + ty * 8 + r;
            const float* vp = vin + ((size_t)(b * SEQ + i) * HW + q) * CV;
            float4 o;
            o.x = mk ? vp[0] : rec[r][0];
            o.y = mk ? vp[1] : rec[r][1];
            o.z = mk ? vp[2] : rec[r][2];
            o.w = 0.f;
            ((float4*)pvn)[q] = o;
            float* op = out_v + ((size_t)(b * NSTEP + i) * HW + q) * CV;
            op[0] = rec[r][0]; op[1] = rec[r][1]; op[2] = rec[r][2];
        }
    }
}

// ---------------- host launcher ----------------------------------------------
extern "C" void kernel_launch(void* const* d_in, const int* in_sizes, int n_in,
                              void* d_out, int out_size) {
    const float* k = (const float*)d_in[0];
    const float* v = (const float*)d_in[1];
    const float* att = (const float*)d_in[2];
    const unsigned char* mask = (const unsigned char*)d_in[3];
    float* out_v = (float*)d_out;
    float* gt = out_v + (size_t)out_size / 2;

    int smem_bytes = (CK * BQ + 2 * 32 * GSTR + 2 * BK * 4) * (int)sizeof(float);  // 205824
    cudaFuncSetAttribute(attend_kernel, cudaFuncAttributeMaxDynamicSharedMemorySize,
                         smem_bytes);

    mask_decode_kernel<<<1, BS * SEQ>>>(mask);
    kt_transpose_kernel<<<dim3(HW / 32, CK / 32, BS * SEQ), dim3(32, 8)>>>(k);
    init_kernel<<<2048, 256>>>(v);
    gt_copy_kernel<<<360, 256>>>(v, gt);

    for (int i = 0; i < NSTEP; i++) {
        int cur = i & 1;
        update_kernel<<<2048, 256>>>(att, i, cur);
        attend_kernel<<<dim3(HW / BQ, BS), 256, smem_bytes>>>(v, out_v, i, cur);
    }
}

// round 6
// speedup vs baseline: 3.5768x; 3.4632x over previous
#include <cuda_runtime.h>
#include <cuda_fp16.h>
#include <cstdint>

#define BS 8
#define SEQ 16
#define HW 1024
#define CK 256
#define CV 3
#define NSTEP 15

#define KTOT 512            // hi‖lo fp16 split-K
#define KC 64               // k chunk (fp16) per smem stage
#define NCHUNKS (KTOT / KC) // 8
#define TM 128
#define TN 128
#define GEMM_BLOCKS (2 * BS * NSTEP * (HW / TM) * (HW / TN))  // 15360
#define GSMEM (2 * 2 * TM * KC * 2)  // 65536

// ---------------- persistent scratch ----------------------------------------
__device__ __align__(256) __half g_k2[(size_t)BS * SEQ * HW * KTOT];
__device__ __align__(256) __half g_m2[(size_t)BS * NSTEP * HW * KTOT];
__device__ float g_S[(size_t)2 * BS * NSTEP * HW * HW];  // logits, both passes
__device__ float g_sig[BS * SEQ * HW];
__device__ __align__(256) float g_mv[BS * HW * 4];
__device__ __align__(256) float g_pv[2][BS * HW * 4];
__device__ int g_mask[BS * SEQ];

// ---------------- PTX helpers ------------------------------------------------
__device__ __forceinline__ uint32_t s2u(const void* p) {
    uint32_t a;
    asm("{ .reg .u64 t; cvta.to.shared.u64 t, %1; cvt.u32.u64 %0, t; }"
        : "=r"(a) : "l"(p));
    return a;
}
#define SWZ(o) ((o) ^ (((o) >> 3) & 0x70))

__device__ __forceinline__ void cp16(uint32_t dst, const void* src) {
    asm volatile("cp.async.cg.shared.global [%0], [%1], 16;" ::"r"(dst), "l"(src));
}
#define CP_COMMIT() asm volatile("cp.async.commit_group;")

__device__ __forceinline__ void ldsm4(uint32_t& r0, uint32_t& r1, uint32_t& r2,
                                      uint32_t& r3, uint32_t addr) {
    asm volatile("ldmatrix.sync.aligned.m8n8.x4.shared.b16 {%0,%1,%2,%3}, [%4];"
                 : "=r"(r0), "=r"(r1), "=r"(r2), "=r"(r3) : "r"(addr));
}
__device__ __forceinline__ void mma16816(float* d, const uint32_t* a,
                                         const uint32_t* b) {
    asm volatile(
        "mma.sync.aligned.m16n8k16.row.col.f32.f16.f16.f32 "
        "{%0,%1,%2,%3}, {%4,%5,%6,%7}, {%8,%9}, {%0,%1,%2,%3};"
        : "+f"(d[0]), "+f"(d[1]), "+f"(d[2]), "+f"(d[3])
        : "r"(a[0]), "r"(a[1]), "r"(a[2]), "r"(a[3]), "r"(b[0]), "r"(b[1]));
}

// ---------------- small kernels ----------------------------------------------
__global__ void mask_decode_kernel(const unsigned char* __restrict__ m) {
    __shared__ int not_i32;
    int t = threadIdx.x;  // 128
    if (t == 0) not_i32 = 0;
    __syncthreads();
    if (t < 32) {
        int w = ((const int*)m)[t];
        if (w != 0 && w != 1) not_i32 = 1;
    }
    __syncthreads();
    g_mask[t] = (!not_i32) ? (((const int*)m)[t] != 0) : (m[t] != 0);
}

__global__ void sig_kernel(const float* __restrict__ att) {
    int e = blockIdx.x * 256 + threadIdx.x;  // 131072
    g_sig[e] = 1.f / (1.f + __expf(-att[e]));
}

__device__ __forceinline__ void split4(__half* hp, __half* lp, float4 x) {
    float xs[4] = {x.x, x.y, x.z, x.w};
#pragma unroll
    for (int u = 0; u < 4; u++) {
        __half h = __float2half(xs[u]);
        __half l = __float2half(xs[u] - __half2float(h));
        hp[u] = h; lp[u] = l;
    }
}

// k -> g_k2 rows of 512 fp16: [0:256)=hi, [256:512)=lo
__global__ void convk_kernel(const float* __restrict__ k) {
    size_t e = (size_t)blockIdx.x * 256 + threadIdx.x;  // 8388608 float4
    float4 x = ((const float4*)k)[e];
    size_t f = 4 * e;
    size_t row = f >> 8;
    int c = (int)(f & 255);
    __half* base = g_k2 + row * KTOT;
    split4(base + c, base + 256 + c, x);
}

// precompute all m_k states (per 16B channel group, loop over steps)
__global__ void mkpre_kernel(const float* __restrict__ k) {
    int t = blockIdx.x * 256 + threadIdx.x;  // 524288
    int cg = t & 63, p = (t >> 6) & 1023, b = t >> 16;
    float4 m = make_float4(0.f, 0.f, 0.f, 0.f);
    for (int s = 0; s < NSTEP; s++) {
        float g = g_sig[(b * SEQ + s) * HW + p];
        float4 kv = *(const float4*)(k + ((size_t)(b * SEQ + s) * HW + p) * CK + cg * 4);
        m.x = g * kv.x + (1.f - g) * m.x;
        m.y = g * kv.y + (1.f - g) * m.y;
        m.z = g * kv.z + (1.f - g) * m.z;
        m.w = g * kv.w + (1.f - g) * m.w;
        __half* base = g_m2 + ((size_t)(b * NSTEP + s) * HW + p) * KTOT;
        split4(base + cg * 4, base + 256 + cg * 4, m);
    }
}

__global__ void init_kernel(const float* __restrict__ v) {
    int t = blockIdx.x * 256 + threadIdx.x;  // 8192
    int b = t >> 10, p = t & 1023;
    ((float4*)g_mv)[t] = make_float4(0.f, 0.f, 0.f, 0.f);
    const float* vp = v + ((size_t)(b * SEQ) * HW + p) * CV;
    ((float4*)g_pv[0])[t] = make_float4(vp[0], vp[1], vp[2], 0.f);
}

__global__ void gt_copy_kernel(const float* __restrict__ v, float* __restrict__ gt) {
    int e = blockIdx.x * blockDim.x + threadIdx.x;  // 92160 float4
    int b = e / (NSTEP * HW * CV / 4);
    int r = e - b * (NSTEP * HW * CV / 4);
    const float4* src = (const float4*)(v + ((size_t)b * SEQ + 1) * HW * CV);
    float4* dst = (float4*)(gt + (size_t)b * NSTEP * HW * CV);
    dst[r] = src[r];
}

__global__ void mv_update_kernel(int i, int cur) {
    int t = blockIdx.x * 256 + threadIdx.x;  // 8192
    int b = t >> 10, p = t & 1023;
    float g = g_sig[(b * SEQ + i) * HW + p];
    float4 pv = ((float4*)g_pv[cur])[t];
    float4 mv = ((float4*)g_mv)[t];
    mv.x = g * pv.x + (1.f - g) * mv.x;
    mv.y = g * pv.y + (1.f - g) * mv.y;
    mv.z = g * pv.z + (1.f - g) * mv.z;
    ((float4*)g_mv)[t] = mv;
}

// ---------------- batched fp16 split-K GEMM (mma.sync / HMMA) ----------------
// block: 256 threads = 8 warps (4 warp_m x 2 warp_n). Block tile 128x128.
// Warp tile 32x64. K = 512 streamed in 64-chunks, double-buffered cp.async.
__global__ __launch_bounds__(256, 2) void gemm_kernel() {
    extern __shared__ char smem[];
    uint32_t sb = s2u(smem);
    int t = threadIdx.x, w = t >> 5, l = t & 31;
    int warp_m = w & 3, warp_n = w >> 2;

    int tile = blockIdx.x;
    int nt = tile & 7, qt = (tile >> 3) & 7;
    int rest = tile >> 6;
    int i = rest % NSTEP; rest /= NSTEP;
    int b = rest & 7, pass = rest >> 3;

    const __half* A = g_k2 + ((size_t)((b * SEQ + i + 1) * HW) + qt * TM) * KTOT;
    const __half* B =
        pass ? g_m2 + ((size_t)((b * NSTEP + i) * HW) + nt * TN) * KTOT
             : g_k2 + ((size_t)((b * SEQ + i) * HW) + nt * TN) * KTOT;

    auto load_chunk = [&](int ch, int buf) {
        uint32_t abase = sb + buf * 32768;
        uint32_t bbase = abase + 16384;
#pragma unroll
        for (int j = 0; j < 4; j++) {
            int idx = j * 256 + t;       // 0..1023
            int row = idx >> 3, k8 = idx & 7;
            uint32_t off = SWZ((uint32_t)(row * 128 + k8 * 16));
            cp16(abase + off, A + (size_t)row * KTOT + ch * KC + k8 * 8);
            cp16(bbase + off, B + (size_t)row * KTOT + ch * KC + k8 * 8);
        }
        CP_COMMIT();
    };

    float acc[2][8][4];
#pragma unroll
    for (int mt = 0; mt < 2; mt++)
#pragma unroll
        for (int n8 = 0; n8 < 8; n8++)
#pragma unroll
            for (int u = 0; u < 4; u++) acc[mt][n8][u] = 0.f;

    load_chunk(0, 0);
    load_chunk(1, 1);

#pragma unroll 1
    for (int c = 0; c < NCHUNKS; c++) {
        if (c < NCHUNKS - 1)
            asm volatile("cp.async.wait_group 1;");
        else
            asm volatile("cp.async.wait_group 0;");
        __syncthreads();

        uint32_t abase = sb + (c & 1) * 32768;
        uint32_t bbase = abase + 16384;
#pragma unroll
        for (int ks = 0; ks < 4; ks++) {
            uint32_t a[2][4];
#pragma unroll
            for (int mt = 0; mt < 2; mt++) {
                int row = warp_m * 32 + mt * 16 + (l & 15);
                int kb = ks * 32 + (l >> 4) * 16;
                ldsm4(a[mt][0], a[mt][1], a[mt][2], a[mt][3],
                      abase + SWZ((uint32_t)(row * 128 + kb)));
            }
            uint32_t bf[4][4];
#pragma unroll
            for (int g16 = 0; g16 < 4; g16++) {
                int n = warp_n * 64 + g16 * 16 + (l >> 4) * 8 + (l & 7);
                int kb = ks * 32 + ((l >> 3) & 1) * 16;
                ldsm4(bf[g16][0], bf[g16][1], bf[g16][2], bf[g16][3],
                      bbase + SWZ((uint32_t)(n * 128 + kb)));
            }
#pragma unroll
            for (int mt = 0; mt < 2; mt++)
#pragma unroll
                for (int n8 = 0; n8 < 8; n8++) {
                    uint32_t bp[2] = {bf[n8 >> 1][(n8 & 1) * 2],
                                      bf[n8 >> 1][(n8 & 1) * 2 + 1]};
                    mma16816(acc[mt][n8], a[mt], bp);
                }
        }
        __syncthreads();
        if (c + 2 < NCHUNKS) load_chunk(c + 2, c & 1);
    }

    // epilogue: write 128x128 fp32 tile
    float* So = g_S + (size_t)((pass * BS + b) * NSTEP + i) * HW * HW +
                (size_t)(qt * TM) * HW + nt * TN;
#pragma unroll
    for (int mt = 0; mt < 2; mt++)
#pragma unroll
        for (int n8 = 0; n8 < 8; n8++) {
            int r0 = warp_m * 32 + mt * 16 + (l >> 2);
            int c0 = warp_n * 64 + n8 * 8 + (l & 3) * 2;
            float2 v01 = make_float2(acc[mt][n8][0], acc[mt][n8][1]);
            float2 v23 = make_float2(acc[mt][n8][2], acc[mt][n8][3]);
            *(float2*)(So + (size_t)r0 * HW + c0) = v01;
            *(float2*)(So + (size_t)(r0 + 8) * HW + c0) = v23;
        }
}

// ---------------- sequential chain: softmax + PV per step --------------------
__global__ __launch_bounds__(256) void softmax_pv_kernel(
    const float* __restrict__ v, float* __restrict__ out_v, int i, int cur) {
    __shared__ float4 Vp[HW];
    __shared__ float4 Vm[HW];
    int t = threadIdx.x;
    int b = blockIdx.x >> 5, rg = blockIdx.x & 31;
#pragma unroll
    for (int j = 0; j < 4; j++) {
        Vp[j * 256 + t] = ((const float4*)g_pv[cur])[b * HW + j * 256 + t];
        Vm[j * 256 + t] = ((const float4*)g_mv)[b * HW + j * 256 + t];
    }
    __syncthreads();

    int w = t >> 5, l = t & 31;
    float recs[4][3];

#pragma unroll 1
    for (int pass = 0; pass < 2; pass++) {
        const float* Sb = g_S + (size_t)((pass * BS + b) * NSTEP + i) * HW * HW;
        const float4* Vs = pass ? Vm : Vp;
        float wgt = pass ? 0.1f : 0.9f;
#pragma unroll 1
        for (int r = 0; r < 4; r++) {
            int q = rg * 32 + w * 4 + r;
            const float* Srow = Sb + (size_t)q * HW;
            float xs[32];
            float mx = -1e30f;
#pragma unroll
            for (int j = 0; j < 32; j++) {
                xs[j] = Srow[j * 32 + l];
                mx = fmaxf(mx, xs[j]);
            }
#pragma unroll
            for (int o = 16; o > 0; o >>= 1)
                mx = fmaxf(mx, __shfl_xor_sync(0xffffffffu, mx, o));
            float s = 0.f, d0 = 0.f, d1 = 0.f, d2 = 0.f;
#pragma unroll
            for (int j = 0; j < 32; j++) {
                float e = __expf(xs[j] - mx);
                float4 vv = Vs[j * 32 + l];
                s += e;
                d0 += e * vv.x; d1 += e * vv.y; d2 += e * vv.z;
            }
#pragma unroll
            for (int o = 16; o > 0; o >>= 1) {
                s += __shfl_xor_sync(0xffffffffu, s, o);
                d0 += __shfl_xor_sync(0xffffffffu, d0, o);
                d1 += __shfl_xor_sync(0xffffffffu, d1, o);
                d2 += __shfl_xor_sync(0xffffffffu, d2, o);
            }
            float inv = wgt / s;
            if (pass == 0) {
                recs[r][0] = d0 * inv; recs[r][1] = d1 * inv; recs[r][2] = d2 * inv;
            } else {
                recs[r][0] += d0 * inv; recs[r][1] += d1 * inv; recs[r][2] += d2 * inv;
            }
        }
    }

    if (l == 0) {
        bool mk = g_mask[b * SEQ + i] != 0;
        float* pvn = g_pv[cur ^ 1] + (size_t)b * HW * 4;
#pragma unroll
        for (int r = 0; r < 4; r++) {
            int q = rg * 32 + w * 4 + r;
            const float* vp = v + ((size_t)(b * SEQ + i) * HW + q) * CV;
            float4 o;
            o.x = mk ? vp[0] : recs[r][0];
            o.y = mk ? vp[1] : recs[r][1];
            o.z = mk ? vp[2] : recs[r][2];
            o.w = 0.f;
            ((float4*)pvn)[q] = o;
            float* op = out_v + ((size_t)(b * NSTEP + i) * HW + q) * CV;
            op[0] = recs[r][0]; op[1] = recs[r][1]; op[2] = recs[r][2];
        }
    }
}

// ---------------- host launcher ----------------------------------------------
extern "C" void kernel_launch(void* const* d_in, const int* in_sizes, int n_in,
                              void* d_out, int out_size) {
    const float* k = (const float*)d_in[0];
    const float* v = (const float*)d_in[1];
    const float* att = (const float*)d_in[2];
    const unsigned char* mask = (const unsigned char*)d_in[3];
    float* out_v = (float*)d_out;
    float* gt = out_v + (size_t)out_size / 2;

    cudaFuncSetAttribute(gemm_kernel, cudaFuncAttributeMaxDynamicSharedMemorySize,
                         GSMEM);

    mask_decode_kernel<<<1, BS * SEQ>>>(mask);
    sig_kernel<<<BS * SEQ * HW / 256, 256>>>(att);
    convk_kernel<<<(int)((size_t)BS * SEQ * HW * CK / 4 / 256), 256>>>(k);
    mkpre_kernel<<<BS * HW * 64 / 256, 256>>>(k);
    init_kernel<<<BS * HW / 256, 256>>>(v);
    gt_copy_kernel<<<360, 256>>>(v, gt);

    gemm_kernel<<<GEMM_BLOCKS, 256, GSMEM>>>();

    for (int i = 0; i < NSTEP; i++) {
        int cur = i & 1;
        mv_update_kernel<<<BS * HW / 256, 256>>>(i, cur);
        softmax_pv_kernel<<<BS * 32, 256>>>(v, out_v, i, cur);
    }
}